// round 4
// baseline (speedup 1.0000x reference)
#include <cuda_runtime.h>
#include <math.h>

#define IN_DIM   512
#define HID      512
#define GRID1    2048
#define BLK1     128    // 128 threads * float4 = 512 columns

// Per-block partial column sums (deterministic, no atomics). 4 MB.
__device__ float g_scratch[GRID1 * IN_DIM];
__device__ float g_agg[IN_DIM];

// ---------------------------------------------------------------------------
// Kernel 1: partial column sums of X (n_rows x 512).
// 128 threads cover one row via float4; 8-way unrolled grid-stride over rows
// -> 8 independent LDG.128 in flight per thread. GRID=2048 -> ~14 blocks/SM
// (occ ~83%) to keep the memory system saturated chip-wide.
// ---------------------------------------------------------------------------
__global__ void __launch_bounds__(BLK1) colsum_kernel(const float* __restrict__ X, int n_rows) {
    const int c4 = threadIdx.x;                 // float4 column index 0..127
    const float4* __restrict__ Xv = (const float4*)X;
    const int S = GRID1;

    float4 acc0 = make_float4(0.f, 0.f, 0.f, 0.f);
    float4 acc1 = make_float4(0.f, 0.f, 0.f, 0.f);
    float4 acc2 = make_float4(0.f, 0.f, 0.f, 0.f);
    float4 acc3 = make_float4(0.f, 0.f, 0.f, 0.f);

    int r = blockIdx.x;
    for (; r + 7 * S < n_rows; r += 8 * S) {
        // 8 independent streaming loads issued back-to-back
        float4 v0 = __ldcs(&Xv[(size_t)(r        ) * 128 + c4]);
        float4 v1 = __ldcs(&Xv[(size_t)(r + 1 * S) * 128 + c4]);
        float4 v2 = __ldcs(&Xv[(size_t)(r + 2 * S) * 128 + c4]);
        float4 v3 = __ldcs(&Xv[(size_t)(r + 3 * S) * 128 + c4]);
        float4 v4 = __ldcs(&Xv[(size_t)(r + 4 * S) * 128 + c4]);
        float4 v5 = __ldcs(&Xv[(size_t)(r + 5 * S) * 128 + c4]);
        float4 v6 = __ldcs(&Xv[(size_t)(r + 6 * S) * 128 + c4]);
        float4 v7 = __ldcs(&Xv[(size_t)(r + 7 * S) * 128 + c4]);
        acc0.x += v0.x; acc0.y += v0.y; acc0.z += v0.z; acc0.w += v0.w;
        acc1.x += v1.x; acc1.y += v1.y; acc1.z += v1.z; acc1.w += v1.w;
        acc2.x += v2.x; acc2.y += v2.y; acc2.z += v2.z; acc2.w += v2.w;
        acc3.x += v3.x; acc3.y += v3.y; acc3.z += v3.z; acc3.w += v3.w;
        acc0.x += v4.x; acc0.y += v4.y; acc0.z += v4.z; acc0.w += v4.w;
        acc1.x += v5.x; acc1.y += v5.y; acc1.z += v5.z; acc1.w += v5.w;
        acc2.x += v6.x; acc2.y += v6.y; acc2.z += v6.z; acc2.w += v6.w;
        acc3.x += v7.x; acc3.y += v7.y; acc3.z += v7.z; acc3.w += v7.w;
    }
    for (; r < n_rows; r += S) {
        float4 v = __ldcs(&Xv[(size_t)r * 128 + c4]);
        acc0.x += v.x; acc0.y += v.y; acc0.z += v.z; acc0.w += v.w;
    }

    float4 s;
    s.x = (acc0.x + acc1.x) + (acc2.x + acc3.x);
    s.y = (acc0.y + acc1.y) + (acc2.y + acc3.y);
    s.z = (acc0.z + acc1.z) + (acc2.z + acc3.z);
    s.w = (acc0.w + acc1.w) + (acc2.w + acc3.w);
    ((float4*)g_scratch)[(size_t)blockIdx.x * 128 + c4] = s;
}

// ---------------------------------------------------------------------------
// Kernel 2: reduce 2048 partial rows -> agg (512 floats). Scratch is
// L2-resident. grid=64, block=256. Block b owns columns [b*8, b*8+8);
// ty in [0,32) strides partial rows -> 64 serial loads/thread, 8-way unrolled.
// ---------------------------------------------------------------------------
__global__ void __launch_bounds__(256) reduce_kernel(float inv_n) {
    __shared__ float part[32][8];
    const int t  = threadIdx.x;
    const int tx = t & 7;
    const int ty = t >> 3;
    const int col = blockIdx.x * 8 + tx;

    float s = 0.f;
    #pragma unroll 8
    for (int p = ty; p < GRID1; p += 32)
        s += g_scratch[p * IN_DIM + col];

    part[ty][tx] = s;
    __syncthreads();
    if (ty == 0) {
        float tot = 0.f;
        #pragma unroll
        for (int k = 0; k < 32; k++)
            tot += part[k][tx];
        g_agg[col] = tot * inv_n;
    }
}

// ---------------------------------------------------------------------------
// Kernel 3: gi = W_ih @ agg + b_ih ; gates with gh = b_hh (h = 0).
// grid=128, block=128 (4 warps). One warp per output i.
// ---------------------------------------------------------------------------
__global__ void __launch_bounds__(128) gru_matvec_kernel(
    const float* __restrict__ W_ih,
    const float* __restrict__ b_ih,
    const float* __restrict__ b_hh,
    float* __restrict__ out)
{
    __shared__ float agg[IN_DIM];
    const int t = threadIdx.x;
    #pragma unroll
    for (int k = 0; k < 4; k++)
        agg[t + k * 128] = g_agg[t + k * 128];
    __syncthreads();

    const int warp = t >> 5;
    const int lane = t & 31;
    const int i = blockIdx.x * 4 + warp;     // output index 0..511
    const float4* __restrict__ aggv = (const float4*)agg;

    float acc[3];
    #pragma unroll
    for (int g = 0; g < 3; g++) {
        const float4* __restrict__ row =
            (const float4*)(W_ih + (size_t)(g * HID + i) * IN_DIM);
        float a = 0.f;
        #pragma unroll
        for (int u = 0; u < 4; u++) {
            float4 w = row[lane + u * 32];
            float4 x = aggv[lane + u * 32];
            a += w.x * x.x + w.y * x.y + w.z * x.z + w.w * x.w;
        }
        #pragma unroll
        for (int off = 16; off; off >>= 1)
            a += __shfl_xor_sync(0xFFFFFFFFu, a, off);
        acc[g] = a;
    }

    if (lane == 0) {
        float gi_r = acc[0] + b_ih[i];
        float gi_z = acc[1] + b_ih[HID + i];
        float gi_n = acc[2] + b_ih[2 * HID + i];
        float r = 1.f / (1.f + __expf(-(gi_r + b_hh[i])));
        float z = 1.f / (1.f + __expf(-(gi_z + b_hh[HID + i])));
        float n = tanhf(gi_n + r * b_hh[2 * HID + i]);
        out[i] = (1.f - z) * n;   // + z*h with h=0
    }
}

extern "C" void kernel_launch(void* const* d_in, const int* in_sizes, int n_in,
                              void* d_out, int out_size) {
    const float* parent_states = (const float*)d_in[0];
    const float* weight_ih     = (const float*)d_in[1];
    // d_in[2] = weight_hh : unused (h = 0 -> W_hh @ h = 0)
    const float* bias_ih       = (const float*)d_in[3];
    const float* bias_hh       = (const float*)d_in[4];
    float* out = (float*)d_out;

    const int n_rows = in_sizes[0] / IN_DIM;
    const float inv_n = 1.0f / (float)n_rows;

    colsum_kernel<<<GRID1, BLK1>>>(parent_states, n_rows);
    reduce_kernel<<<64, 256>>>(inv_n);
    gru_matvec_kernel<<<128, 128>>>(weight_ih, bias_ih, bias_hh, out);
}

// round 5
// speedup vs baseline: 1.1010x; 1.1010x over previous
#include <cuda_runtime.h>
#include <math.h>

#define IN_DIM   512
#define HID      512
#define NSM      148
#define BPSM     12
#define GRID1    (NSM * BPSM)   // 1776: exactly one full wave at 12 blocks/SM
#define BLK1     128            // 128 threads * float4 = 512 columns

// Per-block partial column sums (deterministic, no atomics). ~3.5 MB.
__device__ float g_scratch[GRID1 * IN_DIM];
__device__ float g_agg[IN_DIM];

// ---------------------------------------------------------------------------
// Kernel 1: partial column sums of X (n_rows x 512).
// 128 threads cover one row via float4; 8-way unrolled grid-stride over rows
// -> 8 independent LDG.128 in flight per thread. GRID = 148*12 with
// launch_bounds(128,12): 12 resident blocks/SM, one full wave, no raggedness.
// ---------------------------------------------------------------------------
__global__ void __launch_bounds__(BLK1, BPSM) colsum_kernel(const float* __restrict__ X, int n_rows) {
    const int c4 = threadIdx.x;                 // float4 column index 0..127
    const float4* __restrict__ Xv = (const float4*)X;
    const int S = GRID1;

    float4 acc0 = make_float4(0.f, 0.f, 0.f, 0.f);
    float4 acc1 = make_float4(0.f, 0.f, 0.f, 0.f);
    float4 acc2 = make_float4(0.f, 0.f, 0.f, 0.f);
    float4 acc3 = make_float4(0.f, 0.f, 0.f, 0.f);

    int r = blockIdx.x;
    for (; r + 7 * S < n_rows; r += 8 * S) {
        // 8 independent loads issued back-to-back
        float4 v0 = Xv[(size_t)(r        ) * 128 + c4];
        float4 v1 = Xv[(size_t)(r + 1 * S) * 128 + c4];
        float4 v2 = Xv[(size_t)(r + 2 * S) * 128 + c4];
        float4 v3 = Xv[(size_t)(r + 3 * S) * 128 + c4];
        float4 v4 = Xv[(size_t)(r + 4 * S) * 128 + c4];
        float4 v5 = Xv[(size_t)(r + 5 * S) * 128 + c4];
        float4 v6 = Xv[(size_t)(r + 6 * S) * 128 + c4];
        float4 v7 = Xv[(size_t)(r + 7 * S) * 128 + c4];
        acc0.x += v0.x; acc0.y += v0.y; acc0.z += v0.z; acc0.w += v0.w;
        acc1.x += v1.x; acc1.y += v1.y; acc1.z += v1.z; acc1.w += v1.w;
        acc2.x += v2.x; acc2.y += v2.y; acc2.z += v2.z; acc2.w += v2.w;
        acc3.x += v3.x; acc3.y += v3.y; acc3.z += v3.z; acc3.w += v3.w;
        acc0.x += v4.x; acc0.y += v4.y; acc0.z += v4.z; acc0.w += v4.w;
        acc1.x += v5.x; acc1.y += v5.y; acc1.z += v5.z; acc1.w += v5.w;
        acc2.x += v6.x; acc2.y += v6.y; acc2.z += v6.z; acc2.w += v6.w;
        acc3.x += v7.x; acc3.y += v7.y; acc3.z += v7.z; acc3.w += v7.w;
    }
    for (; r < n_rows; r += S) {
        float4 v = Xv[(size_t)r * 128 + c4];
        acc0.x += v.x; acc0.y += v.y; acc0.z += v.z; acc0.w += v.w;
    }

    float4 s;
    s.x = (acc0.x + acc1.x) + (acc2.x + acc3.x);
    s.y = (acc0.y + acc1.y) + (acc2.y + acc3.y);
    s.z = (acc0.z + acc1.z) + (acc2.z + acc3.z);
    s.w = (acc0.w + acc1.w) + (acc2.w + acc3.w);
    ((float4*)g_scratch)[(size_t)blockIdx.x * 128 + c4] = s;
}

// ---------------------------------------------------------------------------
// Kernel 2: reduce GRID1 partial rows -> agg (512 floats). Scratch is
// L2-resident. grid=64, block=256. Block b owns columns [b*8, b*8+8);
// ty in [0,32) strides partial rows (coalesced 8-col * 32-row tiles).
// ---------------------------------------------------------------------------
__global__ void __launch_bounds__(256) reduce_kernel(float inv_n) {
    __shared__ float part[32][8];
    const int t  = threadIdx.x;
    const int tx = t & 7;
    const int ty = t >> 3;
    const int col = blockIdx.x * 8 + tx;

    float s = 0.f;
    #pragma unroll 8
    for (int p = ty; p < GRID1; p += 32)
        s += g_scratch[p * IN_DIM + col];

    part[ty][tx] = s;
    __syncthreads();
    if (ty == 0) {
        float tot = 0.f;
        #pragma unroll
        for (int k = 0; k < 32; k++)
            tot += part[k][tx];
        g_agg[col] = tot * inv_n;
    }
}

// ---------------------------------------------------------------------------
// Kernel 3: gi = W_ih @ agg + b_ih ; gates with gh = b_hh (h = 0).
// grid=128, block=128 (4 warps). One warp per output i.
// ---------------------------------------------------------------------------
__global__ void __launch_bounds__(128) gru_matvec_kernel(
    const float* __restrict__ W_ih,
    const float* __restrict__ b_ih,
    const float* __restrict__ b_hh,
    float* __restrict__ out)
{
    __shared__ float agg[IN_DIM];
    const int t = threadIdx.x;
    #pragma unroll
    for (int k = 0; k < 4; k++)
        agg[t + k * 128] = g_agg[t + k * 128];
    __syncthreads();

    const int warp = t >> 5;
    const int lane = t & 31;
    const int i = blockIdx.x * 4 + warp;     // output index 0..511
    const float4* __restrict__ aggv = (const float4*)agg;

    float acc[3];
    #pragma unroll
    for (int g = 0; g < 3; g++) {
        const float4* __restrict__ row =
            (const float4*)(W_ih + (size_t)(g * HID + i) * IN_DIM);
        float a = 0.f;
        #pragma unroll
        for (int u = 0; u < 4; u++) {
            float4 w = row[lane + u * 32];
            float4 x = aggv[lane + u * 32];
            a += w.x * x.x + w.y * x.y + w.z * x.z + w.w * x.w;
        }
        #pragma unroll
        for (int off = 16; off; off >>= 1)
            a += __shfl_xor_sync(0xFFFFFFFFu, a, off);
        acc[g] = a;
    }

    if (lane == 0) {
        float gi_r = acc[0] + b_ih[i];
        float gi_z = acc[1] + b_ih[HID + i];
        float gi_n = acc[2] + b_ih[2 * HID + i];
        float r = 1.f / (1.f + __expf(-(gi_r + b_hh[i])));
        float z = 1.f / (1.f + __expf(-(gi_z + b_hh[HID + i])));
        float n = tanhf(gi_n + r * b_hh[2 * HID + i]);
        out[i] = (1.f - z) * n;   // + z*h with h=0
    }
}

extern "C" void kernel_launch(void* const* d_in, const int* in_sizes, int n_in,
                              void* d_out, int out_size) {
    const float* parent_states = (const float*)d_in[0];
    const float* weight_ih     = (const float*)d_in[1];
    // d_in[2] = weight_hh : unused (h = 0 -> W_hh @ h = 0)
    const float* bias_ih       = (const float*)d_in[3];
    const float* bias_hh       = (const float*)d_in[4];
    float* out = (float*)d_out;

    const int n_rows = in_sizes[0] / IN_DIM;
    const float inv_n = 1.0f / (float)n_rows;

    colsum_kernel<<<GRID1, BLK1>>>(parent_states, n_rows);
    reduce_kernel<<<64, 256>>>(inv_n);
    gru_matvec_kernel<<<128, 128>>>(weight_ih, bias_ih, bias_hh, out);
}

// round 6
// speedup vs baseline: 1.1316x; 1.0278x over previous
#include <cuda_runtime.h>
#include <math.h>

#define IN_DIM   512
#define HID      512
#define NSM      148
#define BPSM1    3
#define GRID1    (NSM * BPSM1)   // 444 blocks
#define BLK1     512             // 4 row-workers of 128 threads each
#define NWORK    (GRID1 * 4)     // 1776 row workers, same as R5

// Per-block partial column sums after intra-block reduce. ~0.9 MB.
__device__ float g_scratch[GRID1 * IN_DIM];

// ---------------------------------------------------------------------------
// Kernel 1: partial column sums of X (n_rows x 512).
// Each 128-thread group is one "row worker" (identical load pattern to the
// proven R5 kernel: float4 per thread, 8-way unrolled grid-stride, stride
// NWORK=1776). 4 workers per block reduce through smem -> 1 partial row per
// block, shrinking scratch 4x for the finalize stage.
// ---------------------------------------------------------------------------
__global__ void __launch_bounds__(BLK1, BPSM1) colsum_kernel(const float* __restrict__ X, int n_rows) {
    const int t  = threadIdx.x;
    const int c4 = t & 127;          // float4 column 0..127
    const int g  = t >> 7;           // row-worker group 0..3
    const float4* __restrict__ Xv = (const float4*)X;
    const int S = NWORK;

    float4 acc0 = make_float4(0.f, 0.f, 0.f, 0.f);
    float4 acc1 = make_float4(0.f, 0.f, 0.f, 0.f);
    float4 acc2 = make_float4(0.f, 0.f, 0.f, 0.f);
    float4 acc3 = make_float4(0.f, 0.f, 0.f, 0.f);

    int r = blockIdx.x * 4 + g;
    for (; r + 7 * S < n_rows; r += 8 * S) {
        float4 v0 = Xv[(size_t)(r        ) * 128 + c4];
        float4 v1 = Xv[(size_t)(r + 1 * S) * 128 + c4];
        float4 v2 = Xv[(size_t)(r + 2 * S) * 128 + c4];
        float4 v3 = Xv[(size_t)(r + 3 * S) * 128 + c4];
        float4 v4 = Xv[(size_t)(r + 4 * S) * 128 + c4];
        float4 v5 = Xv[(size_t)(r + 5 * S) * 128 + c4];
        float4 v6 = Xv[(size_t)(r + 6 * S) * 128 + c4];
        float4 v7 = Xv[(size_t)(r + 7 * S) * 128 + c4];
        acc0.x += v0.x; acc0.y += v0.y; acc0.z += v0.z; acc0.w += v0.w;
        acc1.x += v1.x; acc1.y += v1.y; acc1.z += v1.z; acc1.w += v1.w;
        acc2.x += v2.x; acc2.y += v2.y; acc2.z += v2.z; acc2.w += v2.w;
        acc3.x += v3.x; acc3.y += v3.y; acc3.z += v3.z; acc3.w += v3.w;
        acc0.x += v4.x; acc0.y += v4.y; acc0.z += v4.z; acc0.w += v4.w;
        acc1.x += v5.x; acc1.y += v5.y; acc1.z += v5.z; acc1.w += v5.w;
        acc2.x += v6.x; acc2.y += v6.y; acc2.z += v6.z; acc2.w += v6.w;
        acc3.x += v7.x; acc3.y += v7.y; acc3.z += v7.z; acc3.w += v7.w;
    }
    for (; r < n_rows; r += S) {
        float4 v = Xv[(size_t)r * 128 + c4];
        acc0.x += v.x; acc0.y += v.y; acc0.z += v.z; acc0.w += v.w;
    }

    float4 s;
    s.x = (acc0.x + acc1.x) + (acc2.x + acc3.x);
    s.y = (acc0.y + acc1.y) + (acc2.y + acc3.y);
    s.z = (acc0.z + acc1.z) + (acc2.z + acc3.z);
    s.w = (acc0.w + acc1.w) + (acc2.w + acc3.w);

    __shared__ float4 red[3][128];
    if (g > 0) red[g - 1][c4] = s;
    __syncthreads();
    if (g == 0) {
        float4 a = red[0][c4], b = red[1][c4], c = red[2][c4];
        s.x += (a.x + b.x) + c.x;
        s.y += (a.y + b.y) + c.y;
        s.z += (a.z + b.z) + c.z;
        s.w += (a.w + b.w) + c.w;
        ((float4*)g_scratch)[(size_t)blockIdx.x * 128 + c4] = s;
    }
}

// ---------------------------------------------------------------------------
// Kernel 2 (fused finalize): every block redundantly reduces the 0.9 MB
// L2-resident scratch -> agg in smem, then 32 warps compute one GRU output
// each. grid=16, block=1024. gh = b_hh since h = 0 (W_hh never read).
// ---------------------------------------------------------------------------
__global__ void __launch_bounds__(1024, 1) finalize_kernel(
    const float* __restrict__ W_ih,
    const float* __restrict__ b_ih,
    const float* __restrict__ b_hh,
    float* __restrict__ out,
    float inv_n)
{
    __shared__ float4 part[8][128];
    __shared__ float  agg[IN_DIM];
    const int t = threadIdx.x;

    // Phase A: reduce 444 partial rows. 8 row-phases x 128 columns.
    {
        const int c4 = t & 127;
        const int ty = t >> 7;       // 0..7
        const float4* __restrict__ sv = (const float4*)g_scratch;
        float4 s = make_float4(0.f, 0.f, 0.f, 0.f);
        #pragma unroll 8
        for (int p = ty; p < GRID1; p += 8) {
            float4 v = sv[p * 128 + c4];
            s.x += v.x; s.y += v.y; s.z += v.z; s.w += v.w;
        }
        part[ty][c4] = s;
    }
    __syncthreads();
    if (t < 128) {
        float4 s = part[0][t];
        #pragma unroll
        for (int k = 1; k < 8; k++) {
            float4 v = part[k][t];
            s.x += v.x; s.y += v.y; s.z += v.z; s.w += v.w;
        }
        s.x *= inv_n; s.y *= inv_n; s.z *= inv_n; s.w *= inv_n;
        ((float4*)agg)[t] = s;
    }
    __syncthreads();

    // Phase B: one warp per output i.
    const int warp = t >> 5;
    const int lane = t & 31;
    const int i = blockIdx.x * 32 + warp;    // 16 blocks * 32 warps = 512
    const float4* __restrict__ aggv = (const float4*)agg;

    float acc[3];
    #pragma unroll
    for (int g = 0; g < 3; g++) {
        const float4* __restrict__ row =
            (const float4*)(W_ih + (size_t)(g * HID + i) * IN_DIM);
        float a = 0.f;
        #pragma unroll
        for (int u = 0; u < 4; u++) {
            float4 w = row[lane + u * 32];
            float4 x = aggv[lane + u * 32];
            a += w.x * x.x + w.y * x.y + w.z * x.z + w.w * x.w;
        }
        #pragma unroll
        for (int off = 16; off; off >>= 1)
            a += __shfl_xor_sync(0xFFFFFFFFu, a, off);
        acc[g] = a;
    }

    if (lane == 0) {
        float gi_r = acc[0] + b_ih[i];
        float gi_z = acc[1] + b_ih[HID + i];
        float gi_n = acc[2] + b_ih[2 * HID + i];
        float r = 1.f / (1.f + __expf(-(gi_r + b_hh[i])));
        float z = 1.f / (1.f + __expf(-(gi_z + b_hh[HID + i])));
        float n = tanhf(gi_n + r * b_hh[2 * HID + i]);
        out[i] = (1.f - z) * n;   // + z*h with h=0
    }
}

extern "C" void kernel_launch(void* const* d_in, const int* in_sizes, int n_in,
                              void* d_out, int out_size) {
    const float* parent_states = (const float*)d_in[0];
    const float* weight_ih     = (const float*)d_in[1];
    // d_in[2] = weight_hh : unused (h = 0 -> W_hh @ h = 0)
    const float* bias_ih       = (const float*)d_in[3];
    const float* bias_hh       = (const float*)d_in[4];
    float* out = (float*)d_out;

    const int n_rows = in_sizes[0] / IN_DIM;
    const float inv_n = 1.0f / (float)n_rows;

    colsum_kernel<<<GRID1, BLK1>>>(parent_states, n_rows);
    finalize_kernel<<<16, 1024>>>(weight_ih, bias_ih, bias_hh, out, inv_n);
}